// round 15
// baseline (speedup 1.0000x reference)
#include <cuda_runtime.h>
#include <cuda_bf16.h>
#include <cstdint>

#define Bsz 64
#define T   256
#define Isz 2048
#define Hsz 4096
#define Osz 1024

#define THRESHOLD 1.0f
#define DECAY     0.9f

__device__ __nv_bfloat16 g_Ahi[T * Isz];
__device__ __nv_bfloat16 g_Alo[T * Isz];
__device__ float g_cur[T * Hsz];
__device__ float g_agg[Hsz];

__device__ __forceinline__ uint32_t smem_u32(const void* p) {
    uint32_t a;
    asm("{ .reg .u64 t; cvta.to.shared.u64 t, %1; cvt.u32.u64 %0, t; }"
        : "=r"(a) : "l"(p));
    return a;
}
__device__ __forceinline__ void cp16(uint32_t dst, const void* src) {
    asm volatile("cp.async.cg.shared.global [%0], [%1], 16;" :: "r"(dst), "l"(src));
}
__device__ __forceinline__ void cp_commit() {
    asm volatile("cp.async.commit_group;" ::: "memory");
}
template <int N> __device__ __forceinline__ void cp_wait() {
    asm volatile("cp.async.wait_group %0;" :: "n"(N) : "memory");
}
#define LDSM_X4(r0, r1, r2, r3, addr) \
    asm volatile("ldmatrix.sync.aligned.m8n8.x4.shared.b16 {%0,%1,%2,%3}, [%4];" \
                 : "=r"(r0), "=r"(r1), "=r"(r2), "=r"(r3) : "r"(addr))
#define MMA_BF16(d, a, b0, b1) \
    asm volatile("mma.sync.aligned.m16n8k16.row.col.f32.bf16.bf16.f32 " \
                 "{%0,%1,%2,%3}, {%4,%5,%6,%7}, {%8,%9}, {%0,%1,%2,%3};" \
                 : "+f"((d)[0]), "+f"((d)[1]), "+f"((d)[2]), "+f"((d)[3]) \
                 : "r"((a)[0]), "r"((a)[1]), "r"((a)[2]), "r"((a)[3]), \
                   "r"(b0), "r"(b1))

// ---------------------------------------------------------------------------
// 1) Prep: batch reduce x -> A hi/lo only (W is converted inside the GEMM).
// ---------------------------------------------------------------------------
__global__ __launch_bounds__(256) void prep_kernel(const float* __restrict__ x) {
    const int idx = blockIdx.x * 256 + threadIdx.x;
    const int n4  = (T * Isz) / 4;
    const float4* __restrict__ x4 = reinterpret_cast<const float4*>(x);
    float a[4] = {0.f, 0.f, 0.f, 0.f};
#pragma unroll 16
    for (int b = 0; b < Bsz; ++b) {
        float4 v = x4[(size_t)b * n4 + idx];
        a[0] += v.x; a[1] += v.y; a[2] += v.z; a[3] += v.w;
    }
    const float s = 1.0f / (float)Bsz;
    const int base = idx * 4;
#pragma unroll
    for (int i = 0; i < 4; ++i) {
        float v = a[i] * s;
        __nv_bfloat16 hi = __float2bfloat16(v);
        float rem = v - __bfloat162float(hi);
        g_Ahi[base + i] = hi;
        g_Alo[base + i] = __float2bfloat16(rem);
    }
}

// ---------------------------------------------------------------------------
// 2) Warp-specialized HMMA GEMM (see theory above).
// ---------------------------------------------------------------------------
#define LDA_B 272
#define AHI_OFF 0
#define ALO_OFF 17408
#define BHI_OFF 34816
#define BLO_OFF 69632
#define STAGE_B 104448
#define GEMM_SMEM (2 * STAGE_B)
#define NCHUNK 16

__global__ __launch_bounds__(384, 1) void gemm_hmma(const float* __restrict__ W,
                                                    const float* __restrict__ b_in) {
    extern __shared__ char smem[];
    const uint32_t sb = smem_u32(smem);
    const int tid  = threadIdx.x;
    const int lane = tid & 31;
    const int wid  = tid >> 5;
    const int m0 = blockIdx.y * 64;
    const int n0 = blockIdx.x * 128;
    const bool is_compute = (tid < 256);

    const int wm_off = (wid & 1) * 32;
    const int wn_off = ((wid >> 1) & 3) * 32;

    float acc[2][4][4];
#pragma unroll
    for (int i = 0; i < 2; ++i)
#pragma unroll
        for (int j = 0; j < 4; ++j)
#pragma unroll
            for (int k = 0; k < 4; ++k) acc[i][j][k] = 0.f;

    auto stage_base = [&](int c) -> uint32_t {
        return sb + (uint32_t)(c & 1) * STAGE_B;
    };

    auto load_A = [&](int c) {
        const int k0 = c << 7;
        const uint32_t base = stage_base(c);
#pragma unroll
        for (int i = 0; i < 4; ++i) {
            const int idx = i * 256 + tid;
            const int row = idx >> 4, cc = idx & 15;
            const size_t go = (size_t)(m0 + row) * Isz + k0 + cc * 8;
            const uint32_t so = row * LDA_B + cc * 16;
            cp16(base + AHI_OFF + so, &g_Ahi[go]);
            cp16(base + ALO_OFF + so, &g_Alo[go]);
        }
        cp_commit();
    };

    auto produce_B = [&](int c) {
        const int k0 = c << 7;
        const int pid = tid - 256;
        const int pw  = pid >> 5;
        const int pl  = pid & 31;
        const uint32_t bhi = stage_base(c) + BHI_OFF;
        const uint32_t blo = stage_base(c) + BLO_OFF;
#pragma unroll
        for (int g = 0; g < 4; ++g) {
            float4 w[8];
#pragma unroll
            for (int p = 0; p < 4; ++p) {
                const int k = pw * 32 + (g * 4 + p) * 2;
                w[p * 2] = __ldg(reinterpret_cast<const float4*>(
                    &W[(size_t)(k0 + k) * Hsz + n0 + pl * 4]));
                w[p * 2 + 1] = __ldg(reinterpret_cast<const float4*>(
                    &W[(size_t)(k0 + k + 1) * Hsz + n0 + pl * 4]));
            }
#pragma unroll
            for (int p = 0; p < 4; ++p) {
                const int k = pw * 32 + (g * 4 + p) * 2;
                const float* f0 = reinterpret_cast<const float*>(&w[p * 2]);
                const float* f1 = reinterpret_cast<const float*>(&w[p * 2 + 1]);
#pragma unroll
                for (int i = 0; i < 4; ++i) {
                    const int n = pl * 4 + i;
                    const float v0 = f0[i], v1 = f1[i];
                    const __nv_bfloat16 h0 = __float2bfloat16(v0);
                    const __nv_bfloat16 h1 = __float2bfloat16(v1);
                    const uint32_t hp = (uint32_t)__bfloat16_as_ushort(h0) |
                                        ((uint32_t)__bfloat16_as_ushort(h1) << 16);
                    const __nv_bfloat16 l0 =
                        __float2bfloat16(v0 - __bfloat162float(h0));
                    const __nv_bfloat16 l1 =
                        __float2bfloat16(v1 - __bfloat162float(h1));
                    const uint32_t lp = (uint32_t)__bfloat16_as_ushort(l0) |
                                        ((uint32_t)__bfloat16_as_ushort(l1) << 16);
                    const uint32_t off = (uint32_t)n * LDA_B + (uint32_t)k * 2;
                    asm volatile("st.shared.u32 [%0], %1;"
                                 :: "r"(bhi + off), "r"(hp));
                    asm volatile("st.shared.u32 [%0], %1;"
                                 :: "r"(blo + off), "r"(lp));
                }
            }
        }
    };

    const uint32_t a_row_off = (uint32_t)(wm_off + (lane & 15)) * LDA_B;
    const uint32_t b_row_off = (uint32_t)(wn_off + (lane & 15)) * LDA_B;
    const uint32_t k_half    = (uint32_t)((lane >> 4) << 3) * 2;

    if (is_compute) load_A(0);
    else            produce_B(0);

    for (int j = 0; j < NCHUNK; ++j) {
        if (is_compute) cp_wait<0>();
        __syncthreads();

        if (is_compute) {
            if (j + 1 < NCHUNK) load_A(j + 1);
            const uint32_t base = stage_base(j);
#pragma unroll
            for (int k16 = 0; k16 < 8; ++k16) {
                const uint32_t kbyte = (uint32_t)(k16 * 16) * 2 + k_half;
                const uint32_t ar = a_row_off + kbyte;
                const uint32_t br = b_row_off + kbyte;
                uint32_t ahi[2][4], alo[2][4], bhi[2][4], blo[2][4];
#pragma unroll
                for (int mt = 0; mt < 2; ++mt) {
                    const uint32_t ro = ar + mt * 16 * LDA_B;
                    LDSM_X4(ahi[mt][0], ahi[mt][1], ahi[mt][2], ahi[mt][3],
                            base + AHI_OFF + ro);
                    LDSM_X4(alo[mt][0], alo[mt][1], alo[mt][2], alo[mt][3],
                            base + ALO_OFF + ro);
                }
#pragma unroll
                for (int nt2 = 0; nt2 < 2; ++nt2) {
                    const uint32_t ro = br + nt2 * 16 * LDA_B;
                    LDSM_X4(bhi[nt2][0], bhi[nt2][1], bhi[nt2][2], bhi[nt2][3],
                            base + BHI_OFF + ro);
                    LDSM_X4(blo[nt2][0], blo[nt2][1], blo[nt2][2], blo[nt2][3],
                            base + BLO_OFF + ro);
                }
#pragma unroll
                for (int mt = 0; mt < 2; ++mt)
#pragma unroll
                    for (int nt = 0; nt < 4; ++nt) {
                        const int g = nt >> 1, w = nt & 1;
                        MMA_BF16(acc[mt][nt], ahi[mt], bhi[g][w], bhi[g][2 + w]);
                        MMA_BF16(acc[mt][nt], alo[mt], bhi[g][w], bhi[g][2 + w]);
                        MMA_BF16(acc[mt][nt], ahi[mt], blo[g][w], blo[g][2 + w]);
                    }
            }
        } else {
            if (j + 1 < NCHUNK) produce_B(j + 1);
        }
    }

    if (is_compute) {
#pragma unroll
        for (int mt = 0; mt < 2; ++mt) {
#pragma unroll
            for (int nt = 0; nt < 4; ++nt) {
                const int col = n0 + wn_off + nt * 8 + (lane & 3) * 2;
                const float2 bia = *reinterpret_cast<const float2*>(&b_in[col]);
                const int r0 = m0 + wm_off + mt * 16 + (lane >> 2);
                float2 v0, v1;
                v0.x = acc[mt][nt][0] + bia.x;
                v0.y = acc[mt][nt][1] + bia.y;
                v1.x = acc[mt][nt][2] + bia.x;
                v1.y = acc[mt][nt][3] + bia.y;
                *reinterpret_cast<float2*>(&g_cur[(size_t)r0 * Hsz + col]) = v0;
                *reinterpret_cast<float2*>(&g_cur[(size_t)(r0 + 8) * Hsz + col]) = v1;
            }
        }
    }
}

// ---------------------------------------------------------------------------
// 3) LIF scan
// ---------------------------------------------------------------------------
__global__ __launch_bounds__(32) void scan_kernel(const float* __restrict__ m0,
                                                  float* __restrict__ out,
                                                  const float* __restrict__ b_out) {
    const int h = blockIdx.x * 32 + threadIdx.x;
    if (blockIdx.x < Osz / 32) out[h] = b_out[h];

    float m = m0[h];
    float s = 0.f;
    float buf[2][16];
#pragma unroll
    for (int i = 0; i < 16; ++i)
        buf[0][i] = __ldg(&g_cur[(size_t)i * Hsz + h]);

#pragma unroll
    for (int t0 = 0; t0 < T; t0 += 16) {
        const int cur = (t0 >> 4) & 1;
        const int nxt = cur ^ 1;
        if (t0 + 16 < T) {
#pragma unroll
            for (int i = 0; i < 16; ++i)
                buf[nxt][i] = __ldg(&g_cur[(size_t)(t0 + 16 + i) * Hsz + h]);
        }
#pragma unroll
        for (int i = 0; i < 16; ++i) {
            m = DECAY * m + buf[cur][i];
            if (m > THRESHOLD) { s += 1.0f; m = 0.0f; }
        }
    }
    g_agg[h] = s * (1.0f / (float)T);
}

// ---------------------------------------------------------------------------
// 4) Output GEMV
// ---------------------------------------------------------------------------
#define OUT_OB 128
#define OUT_HB 64

__global__ __launch_bounds__(OUT_OB) void out_gemv_kernel(
    const float* __restrict__ W_out, float* __restrict__ out)
{
    __shared__ float s_agg[OUT_HB];
    const int obase = blockIdx.x * OUT_OB;
    const int hbase = blockIdx.y * OUT_HB;
    const int tid   = threadIdx.x;

    if (tid < OUT_HB) s_agg[tid] = g_agg[hbase + tid];
    __syncthreads();

    const int o = obase + tid;
    const float* __restrict__ Wp = &W_out[(size_t)hbase * Osz + o];
    float acc0 = 0.f, acc1 = 0.f;
#pragma unroll
    for (int hh = 0; hh < OUT_HB; hh += 2) {
        acc0 += s_agg[hh]     * Wp[(size_t)hh * Osz];
        acc1 += s_agg[hh + 1] * Wp[(size_t)(hh + 1) * Osz];
    }
    atomicAdd(&out[o], acc0 + acc1);
}

// ---------------------------------------------------------------------------
extern "C" void kernel_launch(void* const* d_in, const int* in_sizes, int n_in,
                              void* d_out, int out_size) {
    const float* x     = (const float*)d_in[0];
    const float* W_in  = (const float*)d_in[1];
    const float* b_in  = (const float*)d_in[2];
    const float* W_out = (const float*)d_in[3];
    const float* b_out = (const float*)d_in[4];
    const float* m0    = (const float*)d_in[5];
    float* out = (float*)d_out;

    // 1) batch reduce only: 512 blocks
    prep_kernel<<<(T * Isz / 4) / 256, 256>>>(x);

    // 2) warp-specialized GEMM: grid (32, 4) = 128 CTAs x 384 threads
    cudaFuncSetAttribute(gemm_hmma,
                         cudaFuncAttributeMaxDynamicSharedMemorySize,
                         GEMM_SMEM);
    dim3 gg(Hsz / 128, T / 64);
    gemm_hmma<<<gg, 384, GEMM_SMEM>>>(W_in, b_in);

    // 3) scan (+ output bias init): 128 blocks x 32 threads
    scan_kernel<<<Hsz / 32, 32>>>(m0, out, b_out);

    // 4) output GEMV: grid (8, 64) = 512 blocks
    dim3 g4(Osz / OUT_OB, Hsz / OUT_HB);
    out_gemv_kernel<<<g4, OUT_OB>>>(W_out, out);
}

// round 16
// speedup vs baseline: 1.5475x; 1.5475x over previous
#include <cuda_runtime.h>
#include <cuda_bf16.h>
#include <cstdint>

#define Bsz 64
#define T   256
#define Isz 2048
#define Hsz 4096
#define Osz 1024

#define THRESHOLD 1.0f
#define DECAY     0.9f

// ---------------- scratch (device globals; no allocation allowed) ----------
__device__ __nv_bfloat16 g_Ahi[T * Isz];     // 1 MB
__device__ __nv_bfloat16 g_Alo[T * Isz];     // 1 MB
__device__ __nv_bfloat16 g_Bhi[Hsz * Isz];   // 16 MB  [N=4096][K=2048] K-major
__device__ __nv_bfloat16 g_Blo[Hsz * Isz];   // 16 MB
__device__ float g_cur[T * Hsz];             // 4 MB
__device__ float g_agg[Hsz];

// ---------------- PTX helpers ----------------------------------------------
__device__ __forceinline__ uint32_t smem_u32(const void* p) {
    uint32_t a;
    asm("{ .reg .u64 t; cvta.to.shared.u64 t, %1; cvt.u32.u64 %0, t; }"
        : "=r"(a) : "l"(p));
    return a;
}
__device__ __forceinline__ void cp16(uint32_t dst, const void* src) {
    asm volatile("cp.async.cg.shared.global [%0], [%1], 16;" :: "r"(dst), "l"(src));
}
__device__ __forceinline__ void cp_commit() {
    asm volatile("cp.async.commit_group;" ::: "memory");
}
template <int N> __device__ __forceinline__ void cp_wait() {
    asm volatile("cp.async.wait_group %0;" :: "n"(N) : "memory");
}
#define LDSM_X4(r0, r1, r2, r3, addr) \
    asm volatile("ldmatrix.sync.aligned.m8n8.x4.shared.b16 {%0,%1,%2,%3}, [%4];" \
                 : "=r"(r0), "=r"(r1), "=r"(r2), "=r"(r3) : "r"(addr))
#define MMA_BF16(d, a, b0, b1) \
    asm volatile("mma.sync.aligned.m16n8k16.row.col.f32.bf16.bf16.f32 " \
                 "{%0,%1,%2,%3}, {%4,%5,%6,%7}, {%8,%9}, {%0,%1,%2,%3};" \
                 : "+f"((d)[0]), "+f"((d)[1]), "+f"((d)[2]), "+f"((d)[3]) \
                 : "r"((a)[0]), "r"((a)[1]), "r"((a)[2]), "r"((a)[3]), \
                   "r"(b0), "r"(b1))

// ---------------------------------------------------------------------------
// 1) Merged prep: blocks [0,512) batch-reduce x -> A hi/lo;
//    blocks [512, 512+4096) transpose+convert W_in -> B hi/lo (packed stores).
// ---------------------------------------------------------------------------
#define RED_BLOCKS 512
__global__ __launch_bounds__(256) void prep_kernel(const float* __restrict__ x,
                                                   const float* __restrict__ W) {
    if (blockIdx.x < RED_BLOCKS) {
        const int idx = blockIdx.x * 256 + threadIdx.x;  // over T*I/4
        const int n4  = (T * Isz) / 4;
        const float4* __restrict__ x4 = reinterpret_cast<const float4*>(x);
        float a[4] = {0.f, 0.f, 0.f, 0.f};
#pragma unroll 16
        for (int b = 0; b < Bsz; ++b) {
            float4 v = x4[(size_t)b * n4 + idx];
            a[0] += v.x; a[1] += v.y; a[2] += v.z; a[3] += v.w;
        }
        const float s = 1.0f / (float)Bsz;
        const int base = idx * 4;
#pragma unroll
        for (int i = 0; i < 4; ++i) {
            float v = a[i] * s;
            __nv_bfloat16 hi = __float2bfloat16(v);
            float rem = v - __bfloat162float(hi);
            g_Ahi[base + i] = hi;
            g_Alo[base + i] = __float2bfloat16(rem);
        }
    } else {
        __shared__ float s[64][33];
        const int bid = blockIdx.x - RED_BLOCKS;       // 0..4095
        const int h0 = (bid & 127) * 32;
        const int i0 = (bid >> 7) * 64;
        const int tc = threadIdx.x & 31;
        const int tr = threadIdx.x >> 5;               // 0..7
#pragma unroll
        for (int j = 0; j < 8; ++j) {
            const int r = tr + j * 8;
            s[r][tc] = W[(size_t)(i0 + r) * Hsz + h0 + tc];
        }
        __syncthreads();
#pragma unroll
        for (int j = 0; j < 4; ++j) {
            const int hl = tr + j * 8;
            const float v0 = s[2 * tc][hl];
            const float v1 = s[2 * tc + 1][hl];
            const __nv_bfloat16 h0b = __float2bfloat16(v0);
            const __nv_bfloat16 h1b = __float2bfloat16(v1);
            const __nv_bfloat16 l0b = __float2bfloat16(v0 - __bfloat162float(h0b));
            const __nv_bfloat16 l1b = __float2bfloat16(v1 - __bfloat162float(h1b));
            const uint32_t hp = (uint32_t)__bfloat16_as_ushort(h0b) |
                                ((uint32_t)__bfloat16_as_ushort(h1b) << 16);
            const uint32_t lp = (uint32_t)__bfloat16_as_ushort(l0b) |
                                ((uint32_t)__bfloat16_as_ushort(l1b) << 16);
            const size_t o = ((size_t)(h0 + hl) * Isz + i0) / 2 + tc;
            reinterpret_cast<uint32_t*>(g_Bhi)[o] = hp;
            reinterpret_cast<uint32_t*>(g_Blo)[o] = lp;
        }
    }
}

// ---------------------------------------------------------------------------
// 2) HMMA bf16 GEMM, fused 3-product hi/lo compensation per k-chunk:
//    acc += Ahi*Bhi + Alo*Bhi + Ahi*Blo   (per BK=128 chunk, tiles loaded once)
//    CTA 64(M)x128(N), 8 warps of 32x32, 2-stage cp.async pipeline (BK=128),
//    double-buffered LDSM fragments, 1 barrier per chunk. MMA-issue bound.
// ---------------------------------------------------------------------------
#define LDA_B 272                        // 128 bf16 (256B) + 16B pad row stride
#define A_TILE_B (64 * LDA_B)            // 17408
#define B_TILE_B (128 * LDA_B)           // 34816
#define STAGE_B  (2 * A_TILE_B + 2 * B_TILE_B)  // 104448
#define NSTAGE 2
#define GEMM_SMEM (NSTAGE * STAGE_B)     // 208896
#define NCHUNK 16                        // 2048 / 128

__global__ __launch_bounds__(256, 1) void gemm_hmma(const float* __restrict__ b_in) {
    extern __shared__ char smem[];
    const uint32_t sb = smem_u32(smem);
    const int tid  = threadIdx.x;
    const int lane = tid & 31;
    const int wid  = tid >> 5;
    const int m0 = blockIdx.y * 64;
    const int n0 = blockIdx.x * 128;

    const int wm_off = (wid & 1) * 32;
    const int wn_off = (wid >> 1) * 32;

    float acc[2][4][4];
#pragma unroll
    for (int i = 0; i < 2; ++i)
#pragma unroll
        for (int j = 0; j < 4; ++j)
#pragma unroll
            for (int k = 0; k < 4; ++k) acc[i][j][k] = 0.f;

    auto stage_base = [&](int c) -> uint32_t {
        return sb + (uint32_t)(c & 1) * STAGE_B;
    };

    // stage layout: [Ahi 17408][Alo 17408][Bhi 34816][Blo 34816]
    auto load_chunk = [&](int c) {
        const int k0 = c << 7;           // 128 k per chunk
        const uint32_t base = stage_base(c);
#pragma unroll
        for (int i = 0; i < 4; ++i) {
            const int idx = i * 256 + tid;
            const int row = idx >> 4, cc = idx & 15;
            const size_t go = (size_t)(m0 + row) * Isz + k0 + cc * 8;
            const uint32_t so = row * LDA_B + cc * 16;
            cp16(base + so, &g_Ahi[go]);
            cp16(base + A_TILE_B + so, &g_Alo[go]);
        }
#pragma unroll
        for (int i = 0; i < 8; ++i) {
            const int idx = i * 256 + tid;
            const int row = idx >> 4, cc = idx & 15;
            const size_t go = (size_t)(n0 + row) * Isz + k0 + cc * 8;
            const uint32_t so = row * LDA_B + cc * 16;
            cp16(base + 2 * A_TILE_B + so, &g_Bhi[go]);
            cp16(base + 2 * A_TILE_B + B_TILE_B + so, &g_Blo[go]);
        }
        cp_commit();
    };

    const uint32_t a_row_off = (uint32_t)(wm_off + (lane & 15)) * LDA_B;
    const uint32_t b_row_off = (uint32_t)(wn_off + (lane & 15)) * LDA_B;
    const uint32_t k_half    = (uint32_t)((lane >> 4) << 3) * 2;  // 0 or 16B

    load_chunk(0);

    for (int j = 0; j < NCHUNK; ++j) {
        cp_wait<0>();       // only load(j) pending here -> wait for it
        __syncthreads();    // all warps done computing stage (j-1)&1

        if (j + 1 < NCHUNK) load_chunk(j + 1);  // writes stage (j+1)&1: safe now

        const uint32_t base  = stage_base(j);
        const uint32_t ahi_b = base;
        const uint32_t alo_b = base + A_TILE_B;
        const uint32_t bhi_b = base + 2 * A_TILE_B;
        const uint32_t blo_b = bhi_b + B_TILE_B;

        uint32_t ahi[2][2][4], alo[2][2][4], bhi[2][2][4], blo[2][2][4];
        auto ldsm_k = [&](int k16, int bf) {
            const uint32_t kbyte = (uint32_t)(k16 * 16) * 2 + k_half;
            const uint32_t ar = a_row_off + kbyte;
            const uint32_t br = b_row_off + kbyte;
#pragma unroll
            for (int mt = 0; mt < 2; ++mt) {
                LDSM_X4(ahi[bf][mt][0], ahi[bf][mt][1], ahi[bf][mt][2], ahi[bf][mt][3],
                        ahi_b + ar + mt * 16 * LDA_B);
                LDSM_X4(alo[bf][mt][0], alo[bf][mt][1], alo[bf][mt][2], alo[bf][mt][3],
                        alo_b + ar + mt * 16 * LDA_B);
            }
#pragma unroll
            for (int nt2 = 0; nt2 < 2; ++nt2) {
                LDSM_X4(bhi[bf][nt2][0], bhi[bf][nt2][1], bhi[bf][nt2][2], bhi[bf][nt2][3],
                        bhi_b + br + nt2 * 16 * LDA_B);
                LDSM_X4(blo[bf][nt2][0], blo[bf][nt2][1], blo[bf][nt2][2], blo[bf][nt2][3],
                        blo_b + br + nt2 * 16 * LDA_B);
            }
        };

        ldsm_k(0, 0);
#pragma unroll
        for (int k16 = 0; k16 < 8; ++k16) {
            const int cur = k16 & 1;
            if (k16 < 7) ldsm_k(k16 + 1, cur ^ 1);
#pragma unroll
            for (int mt = 0; mt < 2; ++mt)
#pragma unroll
                for (int nt = 0; nt < 4; ++nt) {
                    const int g = nt >> 1, w = nt & 1;
                    MMA_BF16(acc[mt][nt], ahi[cur][mt], bhi[cur][g][w], bhi[cur][g][2 + w]);
                    MMA_BF16(acc[mt][nt], alo[cur][mt], bhi[cur][g][w], bhi[cur][g][2 + w]);
                    MMA_BF16(acc[mt][nt], ahi[cur][mt], blo[cur][g][w], blo[cur][g][2 + w]);
                }
        }
    }

    // epilogue: write g_cur with bias
#pragma unroll
    for (int mt = 0; mt < 2; ++mt) {
#pragma unroll
        for (int nt = 0; nt < 4; ++nt) {
            const int col = n0 + wn_off + nt * 8 + (lane & 3) * 2;
            const float2 bia = *reinterpret_cast<const float2*>(&b_in[col]);
            const int r0 = m0 + wm_off + mt * 16 + (lane >> 2);
            float2 v0, v1;
            v0.x = acc[mt][nt][0] + bia.x;
            v0.y = acc[mt][nt][1] + bia.y;
            v1.x = acc[mt][nt][2] + bia.x;
            v1.y = acc[mt][nt][3] + bia.y;
            *reinterpret_cast<float2*>(&g_cur[(size_t)r0 * Hsz + col]) = v0;
            *reinterpret_cast<float2*>(&g_cur[(size_t)(r0 + 8) * Hsz + col]) = v1;
        }
    }
}

// ---------------------------------------------------------------------------
// 3) LIF scan: 128 blocks x 32 threads, software-pipelined 16-deep prefetch.
//    Also initializes out[] = b_out[] (blocks 0..31) ahead of the GEMV.
// ---------------------------------------------------------------------------
__global__ __launch_bounds__(32) void scan_kernel(const float* __restrict__ m0,
                                                  float* __restrict__ out,
                                                  const float* __restrict__ b_out) {
    const int h = blockIdx.x * 32 + threadIdx.x;
    if (blockIdx.x < Osz / 32) out[h] = b_out[h];

    float m = m0[h];
    float s = 0.f;
    float buf[2][16];
#pragma unroll
    for (int i = 0; i < 16; ++i)
        buf[0][i] = __ldg(&g_cur[(size_t)i * Hsz + h]);

#pragma unroll
    for (int t0 = 0; t0 < T; t0 += 16) {
        const int cur = (t0 >> 4) & 1;
        const int nxt = cur ^ 1;
        if (t0 + 16 < T) {
#pragma unroll
            for (int i = 0; i < 16; ++i)
                buf[nxt][i] = __ldg(&g_cur[(size_t)(t0 + 16 + i) * Hsz + h]);
        }
#pragma unroll
        for (int i = 0; i < 16; ++i) {
            m = DECAY * m + buf[cur][i];
            if (m > THRESHOLD) { s += 1.0f; m = 0.0f; }
        }
    }
    g_agg[h] = s * (1.0f / (float)T);
}

// ---------------------------------------------------------------------------
// 4) Output GEMV (out pre-initialized with bias by scan_kernel)
//    OUT_HB=16 -> 2048 blocks (~14 CTAs/SM) for full latency hiding.
// ---------------------------------------------------------------------------
#define OUT_OB 128
#define OUT_HB 16

__global__ __launch_bounds__(OUT_OB) void out_gemv_kernel(
    const float* __restrict__ W_out, float* __restrict__ out)
{
    __shared__ float s_agg[OUT_HB];
    const int obase = blockIdx.x * OUT_OB;
    const int hbase = blockIdx.y * OUT_HB;
    const int tid   = threadIdx.x;

    if (tid < OUT_HB) s_agg[tid] = g_agg[hbase + tid];
    __syncthreads();

    const int o = obase + tid;
    const float* __restrict__ Wp = &W_out[(size_t)hbase * Osz + o];
    // fully unrolled 16-deep load batch -> max MLP, then FMA
    float w[OUT_HB];
#pragma unroll
    for (int hh = 0; hh < OUT_HB; ++hh)
        w[hh] = Wp[(size_t)hh * Osz];
    float acc0 = 0.f, acc1 = 0.f;
#pragma unroll
    for (int hh = 0; hh < OUT_HB; hh += 2) {
        acc0 += s_agg[hh]     * w[hh];
        acc1 += s_agg[hh + 1] * w[hh + 1];
    }
    atomicAdd(&out[o], acc0 + acc1);
}

// ---------------------------------------------------------------------------
extern "C" void kernel_launch(void* const* d_in, const int* in_sizes, int n_in,
                              void* d_out, int out_size) {
    const float* x     = (const float*)d_in[0];  // [B,T,I]
    const float* W_in  = (const float*)d_in[1];  // [I,H]
    const float* b_in  = (const float*)d_in[2];  // [H]
    const float* W_out = (const float*)d_in[3];  // [H,O]
    const float* b_out = (const float*)d_in[4];  // [O]
    const float* m0    = (const float*)d_in[5];  // [H]
    float* out = (float*)d_out;                  // [O]

    // 1) merged reduce + transpose/convert
    prep_kernel<<<RED_BLOCKS + (Hsz / 32) * (Isz / 64), 256>>>(x, W_in);

    // 2) HMMA tensor-core GEMM: grid (32, 4) = 128 CTAs, BK=128, 2 stages
    cudaFuncSetAttribute(gemm_hmma,
                         cudaFuncAttributeMaxDynamicSharedMemorySize,
                         GEMM_SMEM);
    dim3 gg(Hsz / 128, T / 64);
    gemm_hmma<<<gg, 256, GEMM_SMEM>>>(b_in);

    // 3) scan (+ output bias init): 128 blocks x 32 threads
    scan_kernel<<<Hsz / 32, 32>>>(m0, out, b_out);

    // 4) output GEMV: grid (8, 256) = 2048 blocks
    dim3 g4(Osz / OUT_OB, Hsz / OUT_HB);
    out_gemv_kernel<<<g4, OUT_OB>>>(W_out, out);
}